// round 9
// baseline (speedup 1.0000x reference)
#include <cuda_runtime.h>
#include <cstdint>

// CapsuleRouting R8: 16 per-warp pipelines (z-half split), 1 CTA/SM, 512 thr
//  - warp w = (wB = w>>1, wzh = w&1): owns B = wB*18..+17, z = wzh*4..+3
//  - stage = one (B, z-half): 16C x 16p x 4z = 4KB, layout [p][C*4+z] (2-phase LDS.64)
//  - private 3-stage cp.async pipeline per warp, no __syncthreads in main loop
//  - lane = (Cc = lane&15, zq = lane>>4): float2 chains, softmax shuffles masks 1..8
//  - r eliminated (logits linear in v: pass2 dots against w = v0+v1)
//  - `a` input cancels in softmax -> ignored

#define C_N   16
#define P_N   16
#define F2    144
#define XT    8
#define NTILE 18
#define NW    16
#define BPW   18
#define STG_FL  (P_N * 64)          // 1024 floats per stage
#define NSTG  3
#define WSTRIDE (NSTG * STG_FL)     // 3072
#define U_FL  (NW * WSTRIDE)        // 49152
#define V_OFF U_FL
#define PLANE 132
#define V_FL  (C_N * PLANE)         // 2112
#define SMEM_FL (U_FL + V_FL)       // 51264
#define SMEM_BYTES (SMEM_FL * 4)    // 205056 -> 1 CTA/SM
#define BSTRIDE (C_N * P_N * F2)    // 36864 floats per B
#define V_ELEMS (8 * C_N * P_N * F2)

__device__ __forceinline__ void cp_async16(uint32_t s, const float* g) {
    asm volatile("cp.async.cg.shared.global [%0], [%1], 16;" :: "r"(s), "l"(g));
}

// one warp-chunk: 256 granules of 16B (C,p); 8 cp.async per lane
__device__ __forceinline__ void prefetch(const float* __restrict__ gB,
                                         uint32_t dst, int lane) {
#pragma unroll
    for (int k = 0; k < 8; k++) {
        int g = k * 32 + lane;
        int C = g >> 4, p = g & 15;
        cp_async16(dst + 4u * (p * 64 + C * 4), gB + (size_t)(C * P_N + p) * F2);
    }
    asm volatile("cp.async.commit_group;");
}

__global__ void __launch_bounds__(512, 1)
caps_route_kernel(const float* __restrict__ u, float* __restrict__ out) {
    extern __shared__ float sm[];
    const uint32_t smb = (uint32_t)__cvta_generic_to_shared(sm);
    float* v_s = sm + V_OFF;

    const int t = threadIdx.x;
    const int w = t >> 5, lane = t & 31;
    const int wB = w >> 1, wzh = w & 1;
    const int Cc = lane & 15, zq = lane >> 4;      // z = wzh*4 + zq*2 + {0,1}

    const int b  = blockIdx.x / NTILE;
    const int x0 = (blockIdx.x % NTILE) * XT;

    // warp slice base: B-offset, x-offset, z-half folded in
    const float* ubW = u + ((size_t)b * 144 + wB * BPW) * BSTRIDE + x0 + wzh * 4;
    const uint32_t wbase = smb + 4u * (w * WSTRIDE);
    float* wst = sm + w * WSTRIDE;
    const int ld_off = Cc * 4 + zq * 2;            // + p*64

    // squash mapping: t = Cc2*32 + p2*2 + zh2
    const int zh2 = t & 1, p2 = (t >> 1) & 15, Cc2 = t >> 5;

    for (int pass = 0; pass < 3; pass++) {
        float2 vreg[16];
        if (pass) {
#pragma unroll
            for (int p = 0; p < 16; p++)
                vreg[p] = *(const float2*)&v_s[Cc * PLANE + p * 8 + wzh * 4 + zq * 2];
        }
        float2 sreg[16];
#pragma unroll
        for (int p = 0; p < 16; p++) sreg[p] = make_float2(0.f, 0.f);

        if (pass == 0) {   // later passes: j=0,1 issued before previous squash
            prefetch(ubW,           wbase,                lane);
            prefetch(ubW + BSTRIDE, wbase + 4u * STG_FL,  lane);
        }

        for (int j = 0; j < BPW; j++) {
            if (j + 2 < BPW)
                prefetch(ubW + (size_t)(j + 2) * BSTRIDE,
                         wbase + 4u * (((j + 2) % NSTG) * STG_FL), lane);
            if      (j <= BPW - 3) asm volatile("cp.async.wait_group 2;");
            else if (j == BPW - 2) asm volatile("cp.async.wait_group 1;");
            else                   asm volatile("cp.async.wait_group 0;");
            __syncwarp();

            const float* st = wst + (j % NSTG) * STG_FL + ld_off;

            if (pass == 0) {
#pragma unroll
                for (int p = 0; p < 16; p++) {
                    float2 u2 = *(const float2*)&st[p * 64];
                    sreg[p].x += u2.x; sreg[p].y += u2.y;
                }
            } else {
                // dot over p (2 partial chains per component)
                float2 d0 = make_float2(0.f, 0.f), d1 = make_float2(0.f, 0.f);
#pragma unroll
                for (int p = 0; p < 16; p += 2) {
                    float2 a = *(const float2*)&st[p * 64];
                    float2 c = *(const float2*)&st[(p + 1) * 64];
                    d0.x = fmaf(a.x, vreg[p].x,     d0.x);
                    d0.y = fmaf(a.y, vreg[p].y,     d0.y);
                    d1.x = fmaf(c.x, vreg[p + 1].x, d1.x);
                    d1.y = fmaf(c.y, vreg[p + 1].y, d1.y);
                }
                float ex = __expf(d0.x + d1.x);
                float ey = __expf(d0.y + d1.y);
                float sx = ex, sy = ey;
#pragma unroll
                for (int m = 1; m < 16; m <<= 1) {
                    sx += __shfl_xor_sync(0xffffffffu, sx, m);
                    sy += __shfl_xor_sync(0xffffffffu, sy, m);
                }
                const float ccx = __fdividef(ex, sx);
                const float ccy = __fdividef(ey, sy);
#pragma unroll
                for (int p = 0; p < 16; p++) {
                    float2 u2 = *(const float2*)&st[p * 64];
                    sreg[p].x = fmaf(ccx, u2.x, sreg[p].x);
                    sreg[p].y = fmaf(ccy, u2.y, sreg[p].y);
                }
            }
        }

        // partials -> own stage 2 (last-used stage; pipeline drained)
#pragma unroll
        for (int p = 0; p < 16; p++)
            *(float2*)&wst[2 * STG_FL + p * 64 + ld_off] = sreg[p];

        if (pass < 2) {   // overlap next pass's first loads with the exchange
            prefetch(ubW,           wbase,               lane);
            prefetch(ubW + BSTRIDE, wbase + 4u * STG_FL, lane);
        }
        __syncthreads();

        // ---- cross-warp reduce + squash: thread (Cc2, p2, zh2) owns 4 z ----
        {
            const int soff = 2 * STG_FL + p2 * 64 + Cc2 * 4;
            float4 s4 = make_float4(0.f, 0.f, 0.f, 0.f);
#pragma unroll
            for (int wB2 = 0; wB2 < 8; wB2++) {
                float4 a4 = *(const float4*)&sm[(wB2 * 2 + zh2) * WSTRIDE + soff];
                s4.x += a4.x; s4.y += a4.y; s4.z += a4.z; s4.w += a4.w;
            }
            if (pass == 0) {
                s4.x *= 0.0625f; s4.y *= 0.0625f;
                s4.z *= 0.0625f; s4.w *= 0.0625f;
            }
            // sn per (C,z): butterfly over p2 (bits 1..4 of t)
            float4 q = make_float4(s4.x * s4.x, s4.y * s4.y,
                                   s4.z * s4.z, s4.w * s4.w);
#pragma unroll
            for (int m = 2; m < 32; m <<= 1) {
                q.x += __shfl_xor_sync(0xffffffffu, q.x, m);
                q.y += __shfl_xor_sync(0xffffffffu, q.y, m);
                q.z += __shfl_xor_sync(0xffffffffu, q.z, m);
                q.w += __shfl_xor_sync(0xffffffffu, q.w, m);
            }
            float4 k4 = make_float4(sqrtf(q.x) / (1.f + q.x),
                                    sqrtf(q.y) / (1.f + q.y),
                                    sqrtf(q.z) / (1.f + q.z),
                                    sqrtf(q.w) / (1.f + q.w));
            float4 vv = make_float4(s4.x * k4.x, s4.y * k4.y,
                                    s4.z * k4.z, s4.w * k4.w);
            const int voff = Cc2 * PLANE + p2 * 8 + zh2 * 4;
            if (pass < 2) {
                if (pass == 1) {   // store w = v0 + v1 (logits linear in v)
                    float4 o4 = *(const float4*)&v_s[voff];
                    vv.x += o4.x; vv.y += o4.y; vv.z += o4.z; vv.w += o4.w;
                }
                *(float4*)&v_s[voff] = vv;
            } else {
                *(float4*)(out + (((size_t)(b * C_N + Cc2)) * P_N + p2) * F2
                               + x0 + zh2 * 4) = vv;
                if (p2 == 0)
                    *(float4*)(out + (size_t)V_ELEMS
                                   + ((size_t)(b * C_N + Cc2)) * F2 + x0 + zh2 * 4)
                        = make_float4(q.x / (1.f + q.x), q.y / (1.f + q.y),
                                      q.z / (1.f + q.z), q.w / (1.f + q.w));
            }
        }
        __syncthreads();   // v_s visible; stage-2 partials consumed before reuse
    }
}

extern "C" void kernel_launch(void* const* d_in, const int* in_sizes, int n_in,
                              void* d_out, int out_size) {
    const float* u = (const float*)d_in[0];   // (8,144,16,16,12,12) f32
    float* out = (float*)d_out;               // v (8,16,16,144) then a_out (8,16,144)

    cudaFuncSetAttribute(caps_route_kernel,
                         cudaFuncAttributeMaxDynamicSharedMemorySize, SMEM_BYTES);
    caps_route_kernel<<<8 * NTILE, 512, SMEM_BYTES>>>(u, out);
}

// round 10
// speedup vs baseline: 1.1610x; 1.1610x over previous
#include <cuda_runtime.h>
#include <cstdint>

// CapsuleRouting R9: R7 per-warp-pipeline structure, 12 warps, NSTG=2
//  - CTA = (b, x-tile of 8); 144 CTAs, 384 threads
//  - warp w owns B = w*12..+11; stage = one full B (16C x 16p x 32B), double buffer
//  - lane = (zh, Cc): float4 chains; u loaded once/chunk into ureg (dot + accum)
//  - v read from smem in dot (frees 64 regs -> 3 warps/SMSP)
//  - layouts [p][C*8+z] + pad-132 rows: all LDS exact-phase conflict-free
//  - r eliminated (logits linear in v: pass2 dots against w = v0+v1); `a` ignored

#define C_N   16
#define P_N   16
#define F2    144
#define XT    8
#define NTILE 18
#define NW    12
#define BPW   12
#define RPLANE 132                    // words per p-row (528B, 16B-aligned)
#define STG_FL (P_N * RPLANE)         // 2112 floats per stage
#define NSTG  2
#define WSTRIDE (NSTG * STG_FL)       // 4224
#define U_FL  (NW * WSTRIDE)          // 50688
#define V_OFF U_FL
#define V_FL  STG_FL                  // v in same [p][C*8+z] layout
#define SMEM_FL (U_FL + V_FL)         // 52800
#define SMEM_BYTES (SMEM_FL * 4)      // 211200 -> 1 CTA/SM
#define BSTRIDE (C_N * P_N * F2)      // 36864 floats per B
#define V_ELEMS (8 * C_N * P_N * F2)

__device__ __forceinline__ void cp_async16(uint32_t s, const float* g) {
    asm volatile("cp.async.cg.shared.global [%0], [%1], 16;" :: "r"(s), "l"(g));
}

// one B-chunk: 16C x 16p rows of 32B = 512 granules of 16B; 16 cp.async/lane
__device__ __forceinline__ void prefetch(const float* __restrict__ gB,
                                         uint32_t dst, int lane) {
#pragma unroll
    for (int k = 0; k < 16; k++) {
        int q = k * 32 + lane;
        int h = q & 1, C = (q >> 1) & 15, p = q >> 5;
        cp_async16(dst + 4u * (p * RPLANE + C * 8 + h * 4),
                   gB + (size_t)(C * P_N + p) * F2 + h * 4);
    }
    asm volatile("cp.async.commit_group;");
}

__global__ void __launch_bounds__(384, 1)
caps_route_kernel(const float* __restrict__ u, float* __restrict__ out) {
    extern __shared__ float sm[];
    const uint32_t smb = (uint32_t)__cvta_generic_to_shared(sm);
    float* v_s = sm + V_OFF;

    const int t = threadIdx.x;
    const int w = t >> 5, lane = t & 31;
    const int Cc = lane & 15, zh = lane >> 4;   // z = zh*4 + 0..3

    const int b  = blockIdx.x / NTILE;
    const int x0 = (blockIdx.x % NTILE) * XT;

    const float* ubW = u + ((size_t)b * 144 + w * BPW) * BSTRIDE + x0;
    const uint32_t wbase = smb + 4u * (w * WSTRIDE);
    float* wst = sm + w * WSTRIDE;
    const int ld = Cc * 8 + zh * 4;             // + p*RPLANE

    // squash mapping (t < 256): Cc2 = t>>4, p2 = t&15
    const int Cc2 = t >> 4, p2 = t & 15;

    for (int pass = 0; pass < 3; pass++) {
        float4 sreg[16];
#pragma unroll
        for (int p = 0; p < 16; p++) sreg[p] = make_float4(0.f, 0.f, 0.f, 0.f);

        if (pass == 0) {   // later passes: issued around previous squash
            prefetch(ubW,           wbase,               lane);
            prefetch(ubW + BSTRIDE, wbase + 4u * STG_FL, lane);
        }

        for (int j = 0; j < BPW; j++) {
            if (j < BPW - 1) asm volatile("cp.async.wait_group 1;");
            else             asm volatile("cp.async.wait_group 0;");
            __syncwarp();

            const float* st = wst + (j & 1) * STG_FL + ld;
            float4 ureg[16];
#pragma unroll
            for (int p = 0; p < 16; p++)
                ureg[p] = *(const float4*)&st[p * RPLANE];

            if (pass == 0) {
#pragma unroll
                for (int p = 0; p < 16; p++) {
                    sreg[p].x += ureg[p].x; sreg[p].y += ureg[p].y;
                    sreg[p].z += ureg[p].z; sreg[p].w += ureg[p].w;
                }
            } else {
                float4 d = make_float4(0.f, 0.f, 0.f, 0.f);
#pragma unroll
                for (int p = 0; p < 16; p++) {
                    float4 v4 = *(const float4*)&v_s[p * RPLANE + ld];
                    d.x = fmaf(ureg[p].x, v4.x, d.x);
                    d.y = fmaf(ureg[p].y, v4.y, d.y);
                    d.z = fmaf(ureg[p].z, v4.z, d.z);
                    d.w = fmaf(ureg[p].w, v4.w, d.w);
                }
                float4 e = make_float4(__expf(d.x), __expf(d.y),
                                       __expf(d.z), __expf(d.w));
                float4 ss = e;
#pragma unroll
                for (int m = 1; m < 16; m <<= 1) {
                    ss.x += __shfl_xor_sync(0xffffffffu, ss.x, m);
                    ss.y += __shfl_xor_sync(0xffffffffu, ss.y, m);
                    ss.z += __shfl_xor_sync(0xffffffffu, ss.z, m);
                    ss.w += __shfl_xor_sync(0xffffffffu, ss.w, m);
                }
                float4 cc = make_float4(__fdividef(e.x, ss.x),
                                        __fdividef(e.y, ss.y),
                                        __fdividef(e.z, ss.z),
                                        __fdividef(e.w, ss.w));
#pragma unroll
                for (int p = 0; p < 16; p++) {
                    sreg[p].x = fmaf(cc.x, ureg[p].x, sreg[p].x);
                    sreg[p].y = fmaf(cc.y, ureg[p].y, sreg[p].y);
                    sreg[p].z = fmaf(cc.z, ureg[p].z, sreg[p].z);
                    sreg[p].w = fmaf(cc.w, ureg[p].w, sreg[p].w);
                }
            }

            if (j + 2 < BPW)   // stage (j+2)&1 == j&1, just fully consumed
                prefetch(ubW + (size_t)(j + 2) * BSTRIDE,
                         wbase + 4u * ((j & 1) * STG_FL), lane);
        }

        if (pass == 0) {
#pragma unroll
            for (int p = 0; p < 16; p++) {
                sreg[p].x *= 0.0625f; sreg[p].y *= 0.0625f;
                sreg[p].z *= 0.0625f; sreg[p].w *= 0.0625f;
            }
        }
        // partials -> own stage 1 (own reads done; other warps read after barrier)
#pragma unroll
        for (int p = 0; p < 16; p++)
            *(float4*)&wst[STG_FL + p * RPLANE + ld] = sreg[p];

        if (pass < 2)   // overlap: next pass chunk 0 -> stage 0 (free)
            prefetch(ubW, wbase, lane);
        __syncthreads();

        // ---- cross-warp reduce + squash (256 active threads) ----
        if (t < 256) {
            const int soff = STG_FL + p2 * RPLANE + Cc2 * 8;
            float4 sa = make_float4(0.f, 0.f, 0.f, 0.f);
            float4 sb = make_float4(0.f, 0.f, 0.f, 0.f);
#pragma unroll
            for (int w2 = 0; w2 < NW; w2++) {
                float4 a4 = *(const float4*)&sm[w2 * WSTRIDE + soff];
                float4 b4 = *(const float4*)&sm[w2 * WSTRIDE + soff + 4];
                sa.x += a4.x; sa.y += a4.y; sa.z += a4.z; sa.w += a4.w;
                sb.x += b4.x; sb.y += b4.y; sb.z += b4.z; sb.w += b4.w;
            }
            // sn per (C,z): butterfly over p2 (bits 0..3 of lane)
            float4 na = make_float4(sa.x * sa.x, sa.y * sa.y,
                                    sa.z * sa.z, sa.w * sa.w);
            float4 nb = make_float4(sb.x * sb.x, sb.y * sb.y,
                                    sb.z * sb.z, sb.w * sb.w);
#pragma unroll
            for (int m = 1; m < 16; m <<= 1) {
                na.x += __shfl_xor_sync(0xffffffffu, na.x, m);
                na.y += __shfl_xor_sync(0xffffffffu, na.y, m);
                na.z += __shfl_xor_sync(0xffffffffu, na.z, m);
                na.w += __shfl_xor_sync(0xffffffffu, na.w, m);
                nb.x += __shfl_xor_sync(0xffffffffu, nb.x, m);
                nb.y += __shfl_xor_sync(0xffffffffu, nb.y, m);
                nb.z += __shfl_xor_sync(0xffffffffu, nb.z, m);
                nb.w += __shfl_xor_sync(0xffffffffu, nb.w, m);
            }
            float4 ka = make_float4(sqrtf(na.x) / (1.f + na.x),
                                    sqrtf(na.y) / (1.f + na.y),
                                    sqrtf(na.z) / (1.f + na.z),
                                    sqrtf(na.w) / (1.f + na.w));
            float4 kb = make_float4(sqrtf(nb.x) / (1.f + nb.x),
                                    sqrtf(nb.y) / (1.f + nb.y),
                                    sqrtf(nb.z) / (1.f + nb.z),
                                    sqrtf(nb.w) / (1.f + nb.w));
            float4 va = make_float4(sa.x * ka.x, sa.y * ka.y,
                                    sa.z * ka.z, sa.w * ka.w);
            float4 vb = make_float4(sb.x * kb.x, sb.y * kb.y,
                                    sb.z * kb.z, sb.w * kb.w);
            const int voff = p2 * RPLANE + Cc2 * 8;

            if (pass < 2) {
                if (pass == 1) {   // store w = v0 + v1 (logits linear in v)
                    float4 oa = *(const float4*)&v_s[voff];
                    float4 ob = *(const float4*)&v_s[voff + 4];
                    va.x += oa.x; va.y += oa.y; va.z += oa.z; va.w += oa.w;
                    vb.x += ob.x; vb.y += ob.y; vb.z += ob.z; vb.w += ob.w;
                }
                *(float4*)&v_s[voff]     = va;
                *(float4*)&v_s[voff + 4] = vb;
            } else {
                float* og = out + (((size_t)(b * C_N + Cc2)) * P_N + p2) * F2 + x0;
                *(float4*)og       = va;
                *(float4*)(og + 4) = vb;
                if (p2 == 0) {
                    float* oa = out + (size_t)V_ELEMS
                              + ((size_t)(b * C_N + Cc2)) * F2 + x0;
                    *(float4*)oa = make_float4(na.x / (1.f + na.x),
                                               na.y / (1.f + na.y),
                                               na.z / (1.f + na.z),
                                               na.w / (1.f + na.w));
                    *(float4*)(oa + 4) = make_float4(nb.x / (1.f + nb.x),
                                                     nb.y / (1.f + nb.y),
                                                     nb.z / (1.f + nb.z),
                                                     nb.w / (1.f + nb.w));
                }
            }
        }
        __syncthreads();   // v_s + stage-1 partial reads complete

        if (pass < 2)   // chunk 1 -> stage 1 (partials consumed)
            prefetch(ubW + BSTRIDE, wbase + 4u * STG_FL, lane);
    }
}

extern "C" void kernel_launch(void* const* d_in, const int* in_sizes, int n_in,
                              void* d_out, int out_size) {
    const float* u = (const float*)d_in[0];   // (8,144,16,16,12,12) f32
    float* out = (float*)d_out;               // v (8,16,16,144) then a_out (8,16,144)

    cudaFuncSetAttribute(caps_route_kernel,
                         cudaFuncAttributeMaxDynamicSharedMemorySize, SMEM_BYTES);
    caps_route_kernel<<<8 * NTILE, 384, SMEM_BYTES>>>(u, out);
}

// round 11
// speedup vs baseline: 1.3791x; 1.1878x over previous
#include <cuda_runtime.h>
#include <cstdint>

// CapsuleRouting R10: 8 shared B-pipelines, 2 warps each (16 warps, 512 thr)
//  - pair P owns B = P*18..+17; NSTG=3 stages of one full B (16C x 16p x 32B)
//  - load split by C-half (full 32B rows per warp instr -> sector-exact)
//  - compute split by z-half; lane = (Cc, zq): float2 chains
//  - pair sync: named barrier (id P+1, 64 thr), one per chunk
//  - r eliminated (logits linear in v: pass2 dots against w = v0+v1); `a` ignored

#define C_N   16
#define P_N   16
#define F2    144
#define XT    8
#define NTILE 18
#define NPAIR 8
#define BPW   18                     // B per pair
#define PLANE 132                    // p*8+z words per C row + pad
#define STG_FL (C_N * PLANE)         // 2112 floats per stage
#define NSTG  3
#define PSTRIDE (NSTG * STG_FL)      // 6336 per pair
#define U_FL  (NPAIR * PSTRIDE)      // 50688
#define V_OFF U_FL
#define SMEM_FL (U_FL + STG_FL)      // 52800
#define SMEM_BYTES (SMEM_FL * 4)     // 211200 -> 1 CTA/SM
#define BSTRIDE (C_N * P_N * F2)     // 36864 floats per B
#define V_ELEMS (8 * C_N * P_N * F2)

__device__ __forceinline__ void cp_async16(uint32_t s, const float* g) {
    asm volatile("cp.async.cg.shared.global [%0], [%1], 16;" :: "r"(s), "l"(g));
}

// warp loads its C-half of one B (8C x 16p rows of 32B): 8 cp.async/lane
__device__ __forceinline__ void prefetch(const float* __restrict__ gB,
                                         uint32_t dst, int lane, int wc) {
#pragma unroll
    for (int k = 0; k < 8; k++) {
        int q = k * 32 + lane;
        int h = q & 1, p = (q >> 1) & 15, C = wc * 8 + (q >> 5);
        cp_async16(dst + 4u * (C * PLANE + p * 8 + h * 4),
                   gB + (size_t)(C * P_N + p) * F2 + h * 4);
    }
    asm volatile("cp.async.commit_group;");
}

__global__ void __launch_bounds__(512, 1)
caps_route_kernel(const float* __restrict__ u, float* __restrict__ out) {
    extern __shared__ float sm[];
    const uint32_t smb = (uint32_t)__cvta_generic_to_shared(sm);
    float* v_s = sm + V_OFF;

    const int t = threadIdx.x;
    const int w = t >> 5, lane = t & 31;
    const int pair = w >> 1, wz = w & 1;        // wz: C-half for load, z-half for compute
    const int Cc = lane & 15, zq = lane >> 4;   // z = wz*4 + zq*2 + {0,1}
    const int barid = pair + 1;

    const int b  = blockIdx.x / NTILE;
    const int x0 = (blockIdx.x % NTILE) * XT;

    const float* ubP = u + ((size_t)b * 144 + pair * BPW) * BSTRIDE + x0;
    const uint32_t pbase = smb + 4u * (pair * PSTRIDE);
    float* pst = sm + pair * PSTRIDE;
    const int ld = Cc * PLANE + wz * 4 + zq * 2;   // + p*8

    // squash mapping (t < 256): Cc2 = t>>4, p2 = t&15
    const int Cc2 = t >> 4, p2 = t & 15;

    for (int pass = 0; pass < 3; pass++) {
        float2 vreg[16];
        if (pass) {
#pragma unroll
            for (int p = 0; p < 16; p++)
                vreg[p] = *(const float2*)&v_s[ld + p * 8];
        }
        float2 sreg[16];
#pragma unroll
        for (int p = 0; p < 16; p++) sreg[p] = make_float2(0.f, 0.f);

        prefetch(ubP,           pbase,               lane, wz);
        prefetch(ubP + BSTRIDE, pbase + 4u * STG_FL, lane, wz);

        for (int j = 0; j < BPW; j++) {
            if (j < BPW - 1) asm volatile("cp.async.wait_group 1;");
            else             asm volatile("cp.async.wait_group 0;");
            // both halves of chunk j present; both warps done with chunk j-1
            asm volatile("bar.sync %0, 64;" :: "r"(barid) : "memory");

            if (j + 2 < BPW)   // stage (j+2)%3 last read at iter j-1 (pre-bar)
                prefetch(ubP + (size_t)(j + 2) * BSTRIDE,
                         pbase + 4u * (((j + 2) % NSTG) * STG_FL), lane, wz);

            const float* st = pst + (j % NSTG) * STG_FL + ld;
            float2 ureg[16];
#pragma unroll
            for (int p = 0; p < 16; p++)
                ureg[p] = *(const float2*)&st[p * 8];

            if (pass == 0) {
#pragma unroll
                for (int p = 0; p < 16; p++) {
                    sreg[p].x += ureg[p].x; sreg[p].y += ureg[p].y;
                }
            } else {
                float2 d0 = make_float2(0.f, 0.f), d1 = make_float2(0.f, 0.f);
#pragma unroll
                for (int p = 0; p < 16; p += 2) {
                    d0.x = fmaf(ureg[p].x,     vreg[p].x,     d0.x);
                    d0.y = fmaf(ureg[p].y,     vreg[p].y,     d0.y);
                    d1.x = fmaf(ureg[p + 1].x, vreg[p + 1].x, d1.x);
                    d1.y = fmaf(ureg[p + 1].y, vreg[p + 1].y, d1.y);
                }
                float ex = __expf(d0.x + d1.x);
                float ey = __expf(d0.y + d1.y);
                float sx = ex, sy = ey;
#pragma unroll
                for (int m = 1; m < 16; m <<= 1) {
                    sx += __shfl_xor_sync(0xffffffffu, sx, m);
                    sy += __shfl_xor_sync(0xffffffffu, sy, m);
                }
                const float ccx = __fdividef(ex, sx);
                const float ccy = __fdividef(ey, sy);
#pragma unroll
                for (int p = 0; p < 16; p++) {
                    sreg[p].x = fmaf(ccx, ureg[p].x, sreg[p].x);
                    sreg[p].y = fmaf(ccy, ureg[p].y, sreg[p].y);
                }
            }
        }

        if (pass == 0) {
#pragma unroll
            for (int p = 0; p < 16; p++) {
                sreg[p].x *= 0.0625f; sreg[p].y *= 0.0625f;
            }
        }
        // partials -> pair stage 0 (last read at iter 15; both warps past bar 17)
#pragma unroll
        for (int p = 0; p < 16; p++)
            *(float2*)&pst[ld + p * 8] = sreg[p];
        __syncthreads();

        // ---- cross-pair reduce + squash (256 active threads) ----
        if (t < 256) {
            const int soff = Cc2 * PLANE + p2 * 8;
            float4 sa = make_float4(0.f, 0.f, 0.f, 0.f);   // z 0..3
            float4 sb = make_float4(0.f, 0.f, 0.f, 0.f);   // z 4..7
#pragma unroll
            for (int q2 = 0; q2 < NPAIR; q2++) {
                float4 a4 = *(const float4*)&sm[q2 * PSTRIDE + soff];
                float4 b4 = *(const float4*)&sm[q2 * PSTRIDE + soff + 4];
                sa.x += a4.x; sa.y += a4.y; sa.z += a4.z; sa.w += a4.w;
                sb.x += b4.x; sb.y += b4.y; sb.z += b4.z; sb.w += b4.w;
            }
            float4 na = make_float4(sa.x * sa.x, sa.y * sa.y,
                                    sa.z * sa.z, sa.w * sa.w);
            float4 nb = make_float4(sb.x * sb.x, sb.y * sb.y,
                                    sb.z * sb.z, sb.w * sb.w);
#pragma unroll
            for (int m = 1; m < 16; m <<= 1) {
                na.x += __shfl_xor_sync(0xffffffffu, na.x, m);
                na.y += __shfl_xor_sync(0xffffffffu, na.y, m);
                na.z += __shfl_xor_sync(0xffffffffu, na.z, m);
                na.w += __shfl_xor_sync(0xffffffffu, na.w, m);
                nb.x += __shfl_xor_sync(0xffffffffu, nb.x, m);
                nb.y += __shfl_xor_sync(0xffffffffu, nb.y, m);
                nb.z += __shfl_xor_sync(0xffffffffu, nb.z, m);
                nb.w += __shfl_xor_sync(0xffffffffu, nb.w, m);
            }
            float4 ka = make_float4(sqrtf(na.x) / (1.f + na.x),
                                    sqrtf(na.y) / (1.f + na.y),
                                    sqrtf(na.z) / (1.f + na.z),
                                    sqrtf(na.w) / (1.f + na.w));
            float4 kb = make_float4(sqrtf(nb.x) / (1.f + nb.x),
                                    sqrtf(nb.y) / (1.f + nb.y),
                                    sqrtf(nb.z) / (1.f + nb.z),
                                    sqrtf(nb.w) / (1.f + nb.w));
            float4 va = make_float4(sa.x * ka.x, sa.y * ka.y,
                                    sa.z * ka.z, sa.w * ka.w);
            float4 vb = make_float4(sb.x * kb.x, sb.y * kb.y,
                                    sb.z * kb.z, sb.w * kb.w);

            if (pass < 2) {
                if (pass == 1) {   // store w = v0 + v1 (logits linear in v)
                    float4 oa = *(const float4*)&v_s[soff];
                    float4 ob = *(const float4*)&v_s[soff + 4];
                    va.x += oa.x; va.y += oa.y; va.z += oa.z; va.w += oa.w;
                    vb.x += ob.x; vb.y += ob.y; vb.z += ob.z; vb.w += ob.w;
                }
                *(float4*)&v_s[soff]     = va;
                *(float4*)&v_s[soff + 4] = vb;
            } else {
                float* og = out + (((size_t)(b * C_N + Cc2)) * P_N + p2) * F2 + x0;
                *(float4*)og       = va;
                *(float4*)(og + 4) = vb;
                if (p2 == 0) {
                    float* oa = out + (size_t)V_ELEMS
                              + ((size_t)(b * C_N + Cc2)) * F2 + x0;
                    *(float4*)oa = make_float4(na.x / (1.f + na.x),
                                               na.y / (1.f + na.y),
                                               na.z / (1.f + na.z),
                                               na.w / (1.f + na.w));
                    *(float4*)(oa + 4) = make_float4(nb.x / (1.f + nb.x),
                                                     nb.y / (1.f + nb.y),
                                                     nb.z / (1.f + nb.z),
                                                     nb.w / (1.f + nb.w));
                }
            }
        }
        __syncthreads();   // v_s visible; stage-0 partials consumed before reuse
    }
}

extern "C" void kernel_launch(void* const* d_in, const int* in_sizes, int n_in,
                              void* d_out, int out_size) {
    const float* u = (const float*)d_in[0];   // (8,144,16,16,12,12) f32
    float* out = (float*)d_out;               // v (8,16,16,144) then a_out (8,16,144)

    cudaFuncSetAttribute(caps_route_kernel,
                         cudaFuncAttributeMaxDynamicSharedMemorySize, SMEM_BYTES);
    caps_route_kernel<<<8 * NTILE, 512, SMEM_BYTES>>>(u, out);
}

// round 12
// speedup vs baseline: 1.4067x; 1.0200x over previous
#include <cuda_runtime.h>
#include <cstdint>

// CapsuleRouting R11 = R7 + serpentine pass order (L2 turnaround reuse)
//  - CTA = (b, x-tile of 8); 144 CTAs, 256 threads
//  - warp w owns B = w*18..w*18+17, private 3-stage cp.async pipeline
//  - pass 1 walks B in REVERSE: tail of previous pass is L2-resident
//  - lane = (zh, Cc): float4 LDS (conflict-free), 4 z-chains per lane
//  - r eliminated (logits linear in v: pass2 dots against w = v0+v1)
//  - `a` input cancels in softmax -> ignored

#define C_N   16
#define P_N   16
#define F2    144
#define XT    8
#define NTILE 18
#define NW    8
#define BPW   18                    // B per warp
#define PLANE 132                   // P_N*XT + 4 pad
#define STG_FL (C_N * PLANE)        // 2112 floats per stage (one B)
#define NSTG  3
#define WSTRIDE (NSTG * STG_FL)     // 6336 per warp
#define U_FL  (NW * WSTRIDE)        // 50688
#define V_OFF U_FL
#define SMEM_FL (U_FL + STG_FL)     // 52800
#define SMEM_BYTES (SMEM_FL * 4)    // 211200 -> 1 CTA/SM
#define BSTRIDE (C_N * P_N * F2)    // 36864 floats per B
#define V_ELEMS (8 * C_N * P_N * F2)

// serpentine B order: pass 1 reversed
#define BIDX(pass, j) (((pass) == 1) ? (BPW - 1 - (j)) : (j))

__device__ __forceinline__ void cp_async16(uint32_t s, const float* g) {
    asm volatile("cp.async.cg.shared.global [%0], [%1], 16;" :: "r"(s), "l"(g));
}

// load one B-value (16C x 16p rows of 32B) into a warp stage; 16 cp.async/lane
__device__ __forceinline__ void prefetch_B(const float* __restrict__ gB,
                                           uint32_t dst, int lane) {
    const int pl = lane >> 1, h = lane & 1;
    const float* g = gB + (size_t)pl * F2 + h * 4;
    uint32_t d = dst + 4u * (pl * XT + h * 4);
#pragma unroll
    for (int k = 0; k < 16; k++)     // k = C index
        cp_async16(d + 4u * (k * PLANE), g + (size_t)k * (P_N * F2));
    asm volatile("cp.async.commit_group;");
}

__global__ void __launch_bounds__(256, 1)
caps_route_kernel(const float* __restrict__ u, float* __restrict__ out) {
    extern __shared__ float sm[];
    const uint32_t smb = (uint32_t)__cvta_generic_to_shared(sm);
    float* v_s = sm + V_OFF;

    const int t = threadIdx.x;
    const int w = t >> 5, lane = t & 31;
    const int Cc = lane & 15, zh = lane >> 4;      // zh: z-quad 0..3 / 4..7

    const int b  = blockIdx.x / NTILE;
    const int x0 = (blockIdx.x % NTILE) * XT;

    const float* ubW = u + ((size_t)b * 144 + w * BPW) * BSTRIDE + x0;
    const uint32_t wbase = smb + 4u * (w * WSTRIDE);
    float* wstage0 = sm + w * WSTRIDE;

    const int ld_off = Cc * PLANE + zh * 4;        // + p*8 for each p

    for (int pass = 0; pass < 3; pass++) {
        float4 vreg[16];
        if (pass) {
#pragma unroll
            for (int p = 0; p < 16; p++)
                vreg[p] = *(const float4*)&v_s[ld_off + p * 8];
        }
        float4 sreg[16];
#pragma unroll
        for (int p = 0; p < 16; p++) sreg[p] = make_float4(0.f, 0.f, 0.f, 0.f);

        prefetch_B(ubW + (size_t)BIDX(pass, 0) * BSTRIDE, wbase,               lane);
        prefetch_B(ubW + (size_t)BIDX(pass, 1) * BSTRIDE, wbase + 4u * STG_FL, lane);

        for (int j = 0; j < BPW; j++) {
            if (j + 2 < BPW)
                prefetch_B(ubW + (size_t)BIDX(pass, j + 2) * BSTRIDE,
                           wbase + 4u * (((j + 2) % NSTG) * STG_FL), lane);
            // per-warp pacing, no block barrier
            if      (j <= BPW - 3) asm volatile("cp.async.wait_group 2;");
            else if (j == BPW - 2) asm volatile("cp.async.wait_group 1;");
            else                   asm volatile("cp.async.wait_group 0;");
            __syncwarp();

            const float* st = sm + w * WSTRIDE + (j % NSTG) * STG_FL + ld_off;

            if (pass == 0) {
#pragma unroll
                for (int p = 0; p < 16; p++) {
                    float4 u4 = *(const float4*)&st[p * 8];
                    sreg[p].x += u4.x; sreg[p].y += u4.y;
                    sreg[p].z += u4.z; sreg[p].w += u4.w;
                }
            } else {
                float4 d = make_float4(0.f, 0.f, 0.f, 0.f);
#pragma unroll
                for (int p = 0; p < 16; p++) {
                    float4 u4 = *(const float4*)&st[p * 8];
                    d.x = fmaf(u4.x, vreg[p].x, d.x);
                    d.y = fmaf(u4.y, vreg[p].y, d.y);
                    d.z = fmaf(u4.z, vreg[p].z, d.z);
                    d.w = fmaf(u4.w, vreg[p].w, d.w);
                }
                // softmax over C: 16-lane shuffle groups, 4 chains ILP
                float4 e = make_float4(__expf(d.x), __expf(d.y),
                                       __expf(d.z), __expf(d.w));
                float4 ss = e;
#pragma unroll
                for (int m = 1; m < 16; m <<= 1) {
                    ss.x += __shfl_xor_sync(0xffffffffu, ss.x, m);
                    ss.y += __shfl_xor_sync(0xffffffffu, ss.y, m);
                    ss.z += __shfl_xor_sync(0xffffffffu, ss.z, m);
                    ss.w += __shfl_xor_sync(0xffffffffu, ss.w, m);
                }
                float4 cc = make_float4(__fdividef(e.x, ss.x),
                                        __fdividef(e.y, ss.y),
                                        __fdividef(e.z, ss.z),
                                        __fdividef(e.w, ss.w));
#pragma unroll
                for (int p = 0; p < 16; p++) {
                    float4 u4 = *(const float4*)&st[p * 8];
                    sreg[p].x = fmaf(cc.x, u4.x, sreg[p].x);
                    sreg[p].y = fmaf(cc.y, u4.y, sreg[p].y);
                    sreg[p].z = fmaf(cc.z, u4.z, sreg[p].z);
                    sreg[p].w = fmaf(cc.w, u4.w, sreg[p].w);
                }
            }
        }

        // ---- per-warp partial s -> own stage 0 (own pipeline drained) ----
        if (pass == 0) {
#pragma unroll
            for (int p = 0; p < 16; p++) {
                sreg[p].x *= 0.0625f; sreg[p].y *= 0.0625f;
                sreg[p].z *= 0.0625f; sreg[p].w *= 0.0625f;
            }
        }
#pragma unroll
        for (int p = 0; p < 16; p++)
            *(float4*)&wstage0[ld_off + p * 8] = sreg[p];
        __syncthreads();

        // ---- cross-warp reduce + squash: thread t = (Cc2 = t>>4, p2 = t&15)
        {
            const int Cc2 = t >> 4, p2 = t & 15;
            const int roff = Cc2 * PLANE + p2 * 8;
            float4 sa = make_float4(0.f, 0.f, 0.f, 0.f);   // z 0..3
            float4 sb = make_float4(0.f, 0.f, 0.f, 0.f);   // z 4..7
#pragma unroll
            for (int w2 = 0; w2 < NW; w2++) {
                float4 a4 = *(const float4*)&sm[w2 * WSTRIDE + roff];
                float4 b4 = *(const float4*)&sm[w2 * WSTRIDE + roff + 4];
                sa.x += a4.x; sa.y += a4.y; sa.z += a4.z; sa.w += a4.w;
                sb.x += b4.x; sb.y += b4.y; sb.z += b4.z; sb.w += b4.w;
            }
            // sn per (C,z): reduce s^2 over 16 p-lanes (bits 0-3 of t)
            float4 na = make_float4(sa.x * sa.x, sa.y * sa.y,
                                    sa.z * sa.z, sa.w * sa.w);
            float4 nb = make_float4(sb.x * sb.x, sb.y * sb.y,
                                    sb.z * sb.z, sb.w * sb.w);
#pragma unroll
            for (int m = 1; m < 16; m <<= 1) {
                na.x += __shfl_xor_sync(0xffffffffu, na.x, m);
                na.y += __shfl_xor_sync(0xffffffffu, na.y, m);
                na.z += __shfl_xor_sync(0xffffffffu, na.z, m);
                na.w += __shfl_xor_sync(0xffffffffu, na.w, m);
                nb.x += __shfl_xor_sync(0xffffffffu, nb.x, m);
                nb.y += __shfl_xor_sync(0xffffffffu, nb.y, m);
                nb.z += __shfl_xor_sync(0xffffffffu, nb.z, m);
                nb.w += __shfl_xor_sync(0xffffffffu, nb.w, m);
            }
            float4 ka = make_float4(sqrtf(na.x) / (1.f + na.x),
                                    sqrtf(na.y) / (1.f + na.y),
                                    sqrtf(na.z) / (1.f + na.z),
                                    sqrtf(na.w) / (1.f + na.w));
            float4 kb = make_float4(sqrtf(nb.x) / (1.f + nb.x),
                                    sqrtf(nb.y) / (1.f + nb.y),
                                    sqrtf(nb.z) / (1.f + nb.z),
                                    sqrtf(nb.w) / (1.f + nb.w));
            float4 va = make_float4(sa.x * ka.x, sa.y * ka.y,
                                    sa.z * ka.z, sa.w * ka.w);
            float4 vb = make_float4(sb.x * kb.x, sb.y * kb.y,
                                    sb.z * kb.z, sb.w * kb.w);

            if (pass < 2) {
                if (pass == 1) {   // store w = v0 + v1 (logits linear in v)
                    float4 oa = *(const float4*)&v_s[roff];
                    float4 ob = *(const float4*)&v_s[roff + 4];
                    va.x += oa.x; va.y += oa.y; va.z += oa.z; va.w += oa.w;
                    vb.x += ob.x; vb.y += ob.y; vb.z += ob.z; vb.w += ob.w;
                }
                *(float4*)&v_s[roff]     = va;
                *(float4*)&v_s[roff + 4] = vb;
            } else {
                float* og = out + (((size_t)(b * C_N + Cc2)) * P_N + p2) * F2 + x0;
                *(float4*)og       = va;
                *(float4*)(og + 4) = vb;
                if (p2 == 0) {
                    float* oa = out + (size_t)V_ELEMS
                              + ((size_t)(b * C_N + Cc2)) * F2 + x0;
                    *(float4*)oa = make_float4(na.x / (1.f + na.x),
                                               na.y / (1.f + na.y),
                                               na.z / (1.f + na.z),
                                               na.w / (1.f + na.w));
                    *(float4*)(oa + 4) = make_float4(nb.x / (1.f + nb.x),
                                                     nb.y / (1.f + nb.y),
                                                     nb.z / (1.f + nb.z),
                                                     nb.w / (1.f + nb.w));
                }
            }
        }
        __syncthreads();   // v visible; stage-0 partials consumed before reuse
    }
}

extern "C" void kernel_launch(void* const* d_in, const int* in_sizes, int n_in,
                              void* d_out, int out_size) {
    const float* u = (const float*)d_in[0];   // (8,144,16,16,12,12) f32
    float* out = (float*)d_out;               // v (8,16,16,144) then a_out (8,16,144)

    cudaFuncSetAttribute(caps_route_kernel,
                         cudaFuncAttributeMaxDynamicSharedMemorySize, SMEM_BYTES);
    caps_route_kernel<<<8 * NTILE, 256, SMEM_BYTES>>>(u, out);
}